// round 3
// baseline (speedup 1.0000x reference)
#include <cuda_runtime.h>
#include <cuda_bf16.h>
#include <math.h>

#define VOCAB 50257
#define H 1024
#define L 128

// -------- device scratch (no allocations allowed) --------
__device__ float g_scores[L];
__device__ float g_attnw[L];
__device__ float g_attn_applied[H];
__device__ float g_gru_in[H];
__device__ float g_gi[3 * H];
__device__ float g_gh[3 * H];
__device__ float g_hnew[H];

__device__ __forceinline__ float warp_reduce_sum(float v) {
    #pragma unroll
    for (int o = 16; o > 0; o >>= 1) v += __shfl_xor_sync(0xffffffffu, v, o);
    return v;
}

// ---------------------------------------------------------------------------
// K1: scores[l] = dot(attn_W[l, 0:H], q) + dot(attn_W[l, H:2H], h) + attn_b[l]
// warp-per-row, 128 rows. q = emb[input_id] read directly (L2-cached).
// ---------------------------------------------------------------------------
__global__ void k_scores(const int* __restrict__ ids,
                         const float* __restrict__ hidden,
                         const float* __restrict__ emb,
                         const float* __restrict__ attn_W,
                         const float* __restrict__ attn_b) {
    int warp = (blockIdx.x * blockDim.x + threadIdx.x) >> 5;
    int lane = threadIdx.x & 31;
    if (warp >= L) return;
    int id = ids[0];
    const float4* wrow = (const float4*)(attn_W + (size_t)warp * 2 * H);
    const float4* q4 = (const float4*)(emb + (size_t)id * H);
    const float4* h4 = (const float4*)hidden;
    float acc = 0.f;
    #pragma unroll
    for (int k = 0; k < 16; k++) {
        int j = k * 32 + lane;                 // float4 index within 512
        float4 w = wrow[j];
        float4 x = (j < H / 4) ? q4[j] : h4[j - H / 4];
        acc += w.x * x.x + w.y * x.y + w.z * x.z + w.w * x.w;
    }
    acc = warp_reduce_sum(acc);
    if (lane == 0) g_scores[warp] = acc + attn_b[warp];
}

// ---------------------------------------------------------------------------
// K2: softmax over 128 scores -> g_attnw + out attn_weights slot
// ---------------------------------------------------------------------------
__global__ void k_softmax(float* __restrict__ out_attnw) {
    __shared__ float sh[L];
    int t = threadIdx.x;
    float v = g_scores[t];
    sh[t] = v; __syncthreads();
    for (int s = L / 2; s > 0; s >>= 1) {
        if (t < s) sh[t] = fmaxf(sh[t], sh[t + s]);
        __syncthreads();
    }
    float m = sh[0]; __syncthreads();
    float e = expf(v - m);
    sh[t] = e; __syncthreads();
    for (int s = L / 2; s > 0; s >>= 1) {
        if (t < s) sh[t] += sh[t + s];
        __syncthreads();
    }
    float w = e / sh[0];
    g_attnw[t] = w;
    out_attnw[t] = w;
}

// ---------------------------------------------------------------------------
// K3: attn_applied[h] = sum_l w[l] * enc[l, h]   (8 blocks x 128 threads)
// ---------------------------------------------------------------------------
__global__ void k_attn_apply(const float* __restrict__ enc) {
    __shared__ float w[L];
    int t = threadIdx.x;
    w[t] = g_attnw[t];
    __syncthreads();
    int h = blockIdx.x * 128 + t;
    float acc = 0.f;
    #pragma unroll 8
    for (int l = 0; l < L; l++) acc += w[l] * enc[(size_t)l * H + h];
    g_attn_applied[h] = acc;
}

// ---------------------------------------------------------------------------
// K4: gru_in[i] = relu( dot(comb_W[i,0:H], q) + dot(comb_W[i,H:2H], attn) + b )
// warp-per-row, 1024 rows
// ---------------------------------------------------------------------------
__global__ void k_combined(const int* __restrict__ ids,
                           const float* __restrict__ emb,
                           const float* __restrict__ comb_W,
                           const float* __restrict__ comb_b) {
    int warp = (blockIdx.x * blockDim.x + threadIdx.x) >> 5;
    int lane = threadIdx.x & 31;
    if (warp >= H) return;
    int id = ids[0];
    const float4* wrow = (const float4*)(comb_W + (size_t)warp * 2 * H);
    const float4* q4 = (const float4*)(emb + (size_t)id * H);
    const float4* a4 = (const float4*)g_attn_applied;
    float acc = 0.f;
    #pragma unroll
    for (int k = 0; k < 16; k++) {
        int j = k * 32 + lane;
        float4 w = wrow[j];
        float4 x = (j < H / 4) ? q4[j] : a4[j - H / 4];
        acc += w.x * x.x + w.y * x.y + w.z * x.z + w.w * x.w;
    }
    acc = warp_reduce_sum(acc);
    if (lane == 0) g_gru_in[warp] = fmaxf(acc + comb_b[warp], 0.f);
}

// ---------------------------------------------------------------------------
// K5: GRU matvecs. 6144 warp-rows: rows [0,3072) -> gi = W_ih @ gru_in + b_ih,
// rows [3072,6144) -> gh = W_hh @ h + b_hh
// ---------------------------------------------------------------------------
__global__ void k_gru_mv(const float* __restrict__ hidden,
                         const float* __restrict__ W_ih,
                         const float* __restrict__ W_hh,
                         const float* __restrict__ b_ih,
                         const float* __restrict__ b_hh) {
    int warp = (blockIdx.x * blockDim.x + threadIdx.x) >> 5;
    int lane = threadIdx.x & 31;
    if (warp >= 6 * H) return;
    const float4* wrow;
    const float4* x4;
    float bias;
    float* dst;
    if (warp < 3 * H) {
        wrow = (const float4*)(W_ih + (size_t)warp * H);
        x4 = (const float4*)g_gru_in;
        bias = b_ih[warp];
        dst = &g_gi[warp];
    } else {
        int r = warp - 3 * H;
        wrow = (const float4*)(W_hh + (size_t)r * H);
        x4 = (const float4*)hidden;
        bias = b_hh[r];
        dst = &g_gh[r];
    }
    float acc = 0.f;
    #pragma unroll
    for (int k = 0; k < 8; k++) {
        int j = k * 32 + lane;
        float4 w = wrow[j];
        float4 x = x4[j];
        acc += w.x * x.x + w.y * x.y + w.z * x.z + w.w * x.w;
    }
    acc = warp_reduce_sum(acc);
    if (lane == 0) *dst = acc + bias;
}

// ---------------------------------------------------------------------------
// K6: gate combine -> h_new (1 block, 1024 threads)
// ---------------------------------------------------------------------------
__global__ void k_gates(const float* __restrict__ hidden, float* __restrict__ out_h) {
    int i = threadIdx.x;
    float r = 1.f / (1.f + expf(-(g_gi[i] + g_gh[i])));
    float z = 1.f / (1.f + expf(-(g_gi[H + i] + g_gh[H + i])));
    float n = tanhf(g_gi[2 * H + i] + r * g_gh[2 * H + i]);
    float hn = (1.f - z) * n + z * hidden[i];
    g_hnew[i] = hn;
    out_h[i] = hn;
}

// ---------------------------------------------------------------------------
// K7: logits[v] = dot(out_W[v,:], h_new) + out_b[v]  -- THE big one (206 MB)
// 8 warps/block, warp-per-row, h_new in shared. Tail rows clamped (no early
// return around the barrier; predicated store).
// ---------------------------------------------------------------------------
__global__ void __launch_bounds__(256) k_logits(const float* __restrict__ out_W,
                                                const float* __restrict__ out_b,
                                                float* __restrict__ out) {
    __shared__ float4 h4[H / 4];
    int t = threadIdx.x;
    h4[t] = ((const float4*)g_hnew)[t];
    __syncthreads();
    int warp = t >> 5;
    int lane = t & 31;
    int row = blockIdx.x * 8 + warp;
    int rowc = row < VOCAB ? row : (VOCAB - 1);   // clamp: never read OOB
    const float4* wrow = (const float4*)(out_W + (size_t)rowc * H);
    float acc = 0.f;
    #pragma unroll
    for (int k = 0; k < 8; k++) {
        int j = k * 32 + lane;
        float4 w = wrow[j];
        float4 x = h4[j];
        acc += w.x * x.x + w.y * x.y + w.z * x.z + w.w * x.w;
    }
    acc = warp_reduce_sum(acc);
    if (lane == 0 && row < VOCAB) out[row] = acc + out_b[row];
}

// ---------------------------------------------------------------------------
// K8: log_softmax fixup over logits in place (single block; data L2-resident)
// ---------------------------------------------------------------------------
__global__ void k_logsoftmax(float* __restrict__ out) {
    __shared__ float sh[1024];
    int t = threadIdx.x;
    float m = -INFINITY;
    for (int i = t; i < VOCAB; i += 1024) m = fmaxf(m, out[i]);
    sh[t] = m; __syncthreads();
    for (int s = 512; s > 0; s >>= 1) {
        if (t < s) sh[t] = fmaxf(sh[t], sh[t + s]);
        __syncthreads();
    }
    m = sh[0]; __syncthreads();
    float sum = 0.f;
    for (int i = t; i < VOCAB; i += 1024) sum += expf(out[i] - m);
    sh[t] = sum; __syncthreads();
    for (int s = 512; s > 0; s >>= 1) {
        if (t < s) sh[t] += sh[t + s];
        __syncthreads();
    }
    float c = m + logf(sh[0]);
    for (int i = t; i < VOCAB; i += 1024) out[i] -= c;
}

// ---------------------------------------------------------------------------
extern "C" void kernel_launch(void* const* d_in, const int* in_sizes, int n_in,
                              void* d_out, int out_size) {
    const int*   ids    = (const int*)  d_in[0];   // input_ids  [1,1]
    const float* hidden = (const float*)d_in[1];   // hidden     [1,1,H]
    const float* enc    = (const float*)d_in[2];   // encoder_outputs [L,H]
    const float* emb    = (const float*)d_in[3];   // emb        [VOCAB,H]
    const float* attn_W = (const float*)d_in[4];   // [L, 2H]
    const float* attn_b = (const float*)d_in[5];   // [L]
    const float* comb_W = (const float*)d_in[6];   // [H, 2H]
    const float* comb_b = (const float*)d_in[7];   // [H]
    const float* W_ih   = (const float*)d_in[8];   // [3H, H]
    const float* W_hh   = (const float*)d_in[9];   // [3H, H]
    const float* b_ih   = (const float*)d_in[10];  // [3H]
    const float* b_hh   = (const float*)d_in[11];  // [3H]
    const float* out_W  = (const float*)d_in[12];  // [VOCAB, H]
    const float* out_b  = (const float*)d_in[13];  // [VOCAB]

    float* out = (float*)d_out;
    float* out_logp  = out;               // [VOCAB]
    float* out_h     = out + VOCAB;       // [H]
    float* out_attnw = out + VOCAB + H;   // [L]

    // scores: 128 warp-rows -> 32 blocks x 128 threads
    k_scores<<<32, 128>>>(ids, hidden, emb, attn_W, attn_b);
    // softmax over 128
    k_softmax<<<1, 128>>>(out_attnw);
    // attn_applied: 8 blocks x 128 threads
    k_attn_apply<<<8, 128>>>(enc);
    // combined: 1024 warp-rows -> 128 blocks x 256 threads
    k_combined<<<128, 256>>>(ids, emb, comb_W, comb_b);
    // GRU matvecs: 6144 warp-rows -> 768 blocks x 256 threads
    k_gru_mv<<<768, 256>>>(hidden, W_ih, W_hh, b_ih, b_hh);
    // gates
    k_gates<<<1, 1024>>>(hidden, out_h);
    // logits: 50257 warp-rows, 8 per block
    k_logits<<<(VOCAB + 7) / 8, 256>>>(out_W, out_b, out_logp);
    // log_softmax in place
    k_logsoftmax<<<1, 1024>>>(out_logp);
}

// round 5
// speedup vs baseline: 1.2182x; 1.2182x over previous
#include <cuda_runtime.h>
#include <cuda_bf16.h>
#include <math.h>

#define VOCAB 50257
#define H 1024
#define L 128
#define LSE_PARTS 64

// -------- device scratch (no allocations allowed) --------
__device__ float g_spart[4 * L];        // score split-K partials [p][l]
__device__ float g_attnw[L];
__device__ float g_apart[4 * H];        // attn_applied partials  [lc][h]
__device__ float g_cpart[4 * H];        // combined partials      [p][row]
__device__ float g_gi[3 * H];
__device__ float g_gh[3 * H];
__device__ float g_hnew[H];
__device__ float g_pm[LSE_PARTS];       // per-part max
__device__ float g_ps[LSE_PARTS];       // per-part sum exp

__device__ __forceinline__ float warp_reduce_sum(float v) {
    #pragma unroll
    for (int o = 16; o > 0; o >>= 1) v += __shfl_xor_sync(0xffffffffu, v, o);
    return v;
}
__device__ __forceinline__ float warp_reduce_max(float v) {
    #pragma unroll
    for (int o = 16; o > 0; o >>= 1) v = fmaxf(v, __shfl_xor_sync(0xffffffffu, v, o));
    return v;
}

// ---------------------------------------------------------------------------
// K1: scores split-K x4.  512 warps; warp (p, row): partial dot of
// attn_W[row, p*512 : (p+1)*512] with concat(q,h) chunk.
// ---------------------------------------------------------------------------
__global__ void k_scores(const int* __restrict__ ids,
                         const float* __restrict__ hidden,
                         const float* __restrict__ emb,
                         const float* __restrict__ attn_W) {
    int w = (blockIdx.x * blockDim.x + threadIdx.x) >> 5;
    int lane = threadIdx.x & 31;
    if (w >= 4 * L) return;
    int p = w >> 7;           // 0..3
    int row = w & (L - 1);    // 0..127
    int id = ids[0];
    const float4* wrow = (const float4*)(attn_W + (size_t)row * 2 * H);
    const float4* q4 = (const float4*)(emb + (size_t)id * H);
    const float4* h4 = (const float4*)hidden;
    float acc = 0.f;
    #pragma unroll
    for (int k = 0; k < 4; k++) {
        int g = p * 128 + k * 32 + lane;            // float4 idx in [0,512)
        float4 wv = wrow[g];
        float4 x = (g < H / 4) ? q4[g] : h4[g - H / 4];
        acc += wv.x * x.x + wv.y * x.y + wv.z * x.z + wv.w * x.w;
    }
    acc = warp_reduce_sum(acc);
    if (lane == 0) g_spart[p * L + row] = acc;
}

// ---------------------------------------------------------------------------
// K2: combine score partials + bias, softmax over 128 -> g_attnw + out slot
// ---------------------------------------------------------------------------
__global__ void k_softmax(const float* __restrict__ attn_b,
                          float* __restrict__ out_attnw) {
    __shared__ float sh[L];
    int t = threadIdx.x;
    float v = g_spart[t] + g_spart[L + t] + g_spart[2 * L + t] + g_spart[3 * L + t]
            + attn_b[t];
    sh[t] = v; __syncthreads();
    for (int s = L / 2; s > 0; s >>= 1) {
        if (t < s) sh[t] = fmaxf(sh[t], sh[t + s]);
        __syncthreads();
    }
    float m = sh[0]; __syncthreads();
    float e = expf(v - m);
    sh[t] = e; __syncthreads();
    for (int s = L / 2; s > 0; s >>= 1) {
        if (t < s) sh[t] += sh[t + s];
        __syncthreads();
    }
    float wv = e / sh[0];
    g_attnw[t] = wv;
    out_attnw[t] = wv;
}

// ---------------------------------------------------------------------------
// K3: attn_applied partials: 32 blocks (lc = b>>3, hb = b&7) x 128 threads.
// g_apart[lc][h] = sum_{l in chunk lc} w[l] * enc[l, h]
// ---------------------------------------------------------------------------
__global__ void k_attn_apply(const float* __restrict__ enc) {
    __shared__ float w[32];
    int lc = blockIdx.x >> 3;
    int hb = blockIdx.x & 7;
    int t = threadIdx.x;
    if (t < 32) w[t] = g_attnw[lc * 32 + t];
    __syncthreads();
    int h = hb * 128 + t;
    const float* base = enc + (size_t)(lc * 32) * H + h;
    float acc = 0.f;
    #pragma unroll
    for (int l = 0; l < 32; l++) acc += w[l] * base[(size_t)l * H];
    g_apart[lc * H + h] = acc;
}

// ---------------------------------------------------------------------------
// K4: combined split-K x4. 4096 warps; warp (row = w>>2, p = w&3).
// x chunk: concat(q, attn_applied) where attn element = sum of 4 g_apart.
// ---------------------------------------------------------------------------
__global__ void k_combined(const int* __restrict__ ids,
                           const float* __restrict__ emb,
                           const float* __restrict__ comb_W) {
    int w = (blockIdx.x * blockDim.x + threadIdx.x) >> 5;
    int lane = threadIdx.x & 31;
    if (w >= 4 * H) return;
    int row = w >> 2;
    int p = w & 3;
    int id = ids[0];
    const float4* wrow = (const float4*)(comb_W + (size_t)row * 2 * H);
    const float4* q4 = (const float4*)(emb + (size_t)id * H);
    const float4* a4 = (const float4*)g_apart;  // [4][256] float4
    float acc = 0.f;
    #pragma unroll
    for (int k = 0; k < 4; k++) {
        int g = p * 128 + k * 32 + lane;            // float4 idx in [0,512)
        float4 wv = wrow[g];
        float4 x;
        if (g < H / 4) {
            x = q4[g];
        } else {
            int a = g - H / 4;                      // 0..255
            float4 x0 = a4[a], x1 = a4[256 + a], x2 = a4[512 + a], x3 = a4[768 + a];
            x.x = x0.x + x1.x + x2.x + x3.x;
            x.y = x0.y + x1.y + x2.y + x3.y;
            x.z = x0.z + x1.z + x2.z + x3.z;
            x.w = x0.w + x1.w + x2.w + x3.w;
        }
        acc += wv.x * x.x + wv.y * x.y + wv.z * x.z + wv.w * x.w;
    }
    acc = warp_reduce_sum(acc);
    if (lane == 0) g_cpart[p * H + row] = acc;
}

// ---------------------------------------------------------------------------
// K5: GRU matvecs. 6144 warp-rows. ih-half recomputes gru_in elementwise
// on the fly from combined partials (L2-resident): relu(sum cpart + comb_b).
// ---------------------------------------------------------------------------
__global__ void k_gru_mv(const float* __restrict__ hidden,
                         const float* __restrict__ W_ih,
                         const float* __restrict__ W_hh,
                         const float* __restrict__ b_ih,
                         const float* __restrict__ b_hh,
                         const float* __restrict__ comb_b) {
    int w = (blockIdx.x * blockDim.x + threadIdx.x) >> 5;
    int lane = threadIdx.x & 31;
    if (w >= 6 * H) return;
    float acc = 0.f;
    if (w < 3 * H) {
        const float4* wrow = (const float4*)(W_ih + (size_t)w * H);
        const float4* c4 = (const float4*)g_cpart;   // [4][256] float4
        const float4* b4 = (const float4*)comb_b;
        #pragma unroll
        for (int k = 0; k < 8; k++) {
            int j = k * 32 + lane;
            float4 wv = wrow[j];
            float4 x0 = c4[j], x1 = c4[256 + j], x2 = c4[512 + j], x3 = c4[768 + j];
            float4 bb = b4[j];
            float4 x;
            x.x = fmaxf(x0.x + x1.x + x2.x + x3.x + bb.x, 0.f);
            x.y = fmaxf(x0.y + x1.y + x2.y + x3.y + bb.y, 0.f);
            x.z = fmaxf(x0.z + x1.z + x2.z + x3.z + bb.z, 0.f);
            x.w = fmaxf(x0.w + x1.w + x2.w + x3.w + bb.w, 0.f);
            acc += wv.x * x.x + wv.y * x.y + wv.z * x.z + wv.w * x.w;
        }
        acc = warp_reduce_sum(acc);
        if (lane == 0) g_gi[w] = acc + b_ih[w];
    } else {
        int r = w - 3 * H;
        const float4* wrow = (const float4*)(W_hh + (size_t)r * H);
        const float4* x4 = (const float4*)hidden;
        #pragma unroll
        for (int k = 0; k < 8; k++) {
            int j = k * 32 + lane;
            float4 wv = wrow[j];
            float4 x = x4[j];
            acc += wv.x * x.x + wv.y * x.y + wv.z * x.z + wv.w * x.w;
        }
        acc = warp_reduce_sum(acc);
        if (lane == 0) g_gh[r] = acc + b_hh[r];
    }
}

// ---------------------------------------------------------------------------
// K6: gate combine -> h_new (1 block, 1024 threads)
// ---------------------------------------------------------------------------
__global__ void k_gates(const float* __restrict__ hidden, float* __restrict__ out_h) {
    int i = threadIdx.x;
    float r = 1.f / (1.f + expf(-(g_gi[i] + g_gh[i])));
    float z = 1.f / (1.f + expf(-(g_gi[H + i] + g_gh[H + i])));
    float n = tanhf(g_gi[2 * H + i] + r * g_gh[2 * H + i]);
    float hn = (1.f - z) * n + z * hidden[i];
    g_hnew[i] = hn;
    out_h[i] = hn;
}

// ---------------------------------------------------------------------------
// K7: logits. 4 rows per warp (2-row interleave -> 16 outstanding LDG.128),
// x cached in registers (8 float4/lane, same j across rows). No smem barrier.
// ---------------------------------------------------------------------------
__global__ void __launch_bounds__(256) k_logits(const float* __restrict__ out_W,
                                                const float* __restrict__ out_b,
                                                float* __restrict__ out) {
    int t = threadIdx.x;
    int warp = t >> 5;
    int lane = t & 31;
    int rbase = (blockIdx.x * 8 + warp) * 4;

    // load x once into registers
    float4 xr[8];
    const float4* h4 = (const float4*)g_hnew;
    #pragma unroll
    for (int k = 0; k < 8; k++) xr[k] = __ldg(&h4[k * 32 + lane]);

    #pragma unroll
    for (int pair = 0; pair < 2; pair++) {
        int r0 = rbase + pair * 2;
        int r1 = r0 + 1;
        int r0c = r0 < VOCAB ? r0 : (VOCAB - 1);
        int r1c = r1 < VOCAB ? r1 : (VOCAB - 1);
        const float4* w0 = (const float4*)(out_W + (size_t)r0c * H);
        const float4* w1 = (const float4*)(out_W + (size_t)r1c * H);
        float a0 = 0.f, a1 = 0.f;
        #pragma unroll
        for (int k = 0; k < 8; k++) {
            int j = k * 32 + lane;
            float4 v0 = w0[j];
            float4 v1 = w1[j];
            float4 x = xr[k];
            a0 += v0.x * x.x + v0.y * x.y + v0.z * x.z + v0.w * x.w;
            a1 += v1.x * x.x + v1.y * x.y + v1.z * x.z + v1.w * x.w;
        }
        a0 = warp_reduce_sum(a0);
        a1 = warp_reduce_sum(a1);
        if (lane == 0 && r0 < VOCAB) out[r0] = a0 + out_b[r0];
        if (lane == 0 && r1 < VOCAB) out[r1] = a1 + out_b[r1];
    }
}

// ---------------------------------------------------------------------------
// K8: LSE partials: 64 blocks x 256 threads, grid-stride. (m_b, s_b) per block.
// ---------------------------------------------------------------------------
__global__ void k_lse_part(const float* __restrict__ out) {
    __shared__ float sh[256];
    int t = threadIdx.x;
    int b = blockIdx.x;
    const int stride = LSE_PARTS * 256;

    float m = -INFINITY;
    for (int i = b * 256 + t; i < VOCAB; i += stride) m = fmaxf(m, out[i]);
    sh[t] = m; __syncthreads();
    for (int s = 128; s > 0; s >>= 1) {
        if (t < s) sh[t] = fmaxf(sh[t], sh[t + s]);
        __syncthreads();
    }
    m = sh[0]; __syncthreads();

    float sum = 0.f;
    for (int i = b * 256 + t; i < VOCAB; i += stride) sum += expf(out[i] - m);
    sh[t] = sum; __syncthreads();
    for (int s = 128; s > 0; s >>= 1) {
        if (t < s) sh[t] += sh[t + s];
        __syncthreads();
    }
    if (t == 0) { g_pm[b] = m; g_ps[b] = sh[0]; }
}

// ---------------------------------------------------------------------------
// K9: combine 64 partials per block (cheap, L2) and subtract c in place.
// ---------------------------------------------------------------------------
__global__ void k_lse_apply(float* __restrict__ out) {
    __shared__ float shc;
    int t = threadIdx.x;
    if (t < 32) {
        float m0 = g_pm[t], m1 = g_pm[t + 32];
        float M = warp_reduce_max(fmaxf(m0, m1));
        float s = g_ps[t] * expf(m0 - M) + g_ps[t + 32] * expf(m1 - M);
        s = warp_reduce_sum(s);
        if (t == 0) shc = M + logf(s);
    }
    __syncthreads();
    float c = shc;
    int i = blockIdx.x * 256 + t;
    if (i < VOCAB) out[i] -= c;
}

// ---------------------------------------------------------------------------
extern "C" void kernel_launch(void* const* d_in, const int* in_sizes, int n_in,
                              void* d_out, int out_size) {
    const int*   ids    = (const int*)  d_in[0];   // input_ids  [1,1]
    const float* hidden = (const float*)d_in[1];   // hidden     [1,1,H]
    const float* enc    = (const float*)d_in[2];   // encoder_outputs [L,H]
    const float* emb    = (const float*)d_in[3];   // emb        [VOCAB,H]
    const float* attn_W = (const float*)d_in[4];   // [L, 2H]
    const float* attn_b = (const float*)d_in[5];   // [L]
    const float* comb_W = (const float*)d_in[6];   // [H, 2H]
    const float* comb_b = (const float*)d_in[7];   // [H]
    const float* W_ih   = (const float*)d_in[8];   // [3H, H]
    const float* W_hh   = (const float*)d_in[9];   // [3H, H]
    const float* b_ih   = (const float*)d_in[10];  // [3H]
    const float* b_hh   = (const float*)d_in[11];  // [3H]
    const float* out_W  = (const float*)d_in[12];  // [VOCAB, H]
    const float* out_b  = (const float*)d_in[13];  // [VOCAB]

    float* out = (float*)d_out;
    float* out_logp  = out;               // [VOCAB]
    float* out_h     = out + VOCAB;       // [H]
    float* out_attnw = out + VOCAB + H;   // [L]

    k_scores<<<64, 256>>>(ids, hidden, emb, attn_W);          // 512 warps, splitK x4
    k_softmax<<<1, 128>>>(attn_b, out_attnw);
    k_attn_apply<<<32, 128>>>(enc);                           // 4 L-chunks x 8 h-blocks
    k_combined<<<512, 256>>>(ids, emb, comb_W);               // 4096 warps, splitK x4
    k_gru_mv<<<768, 256>>>(hidden, W_ih, W_hh, b_ih, b_hh, comb_b);
    k_gates<<<1, 1024>>>(hidden, out_h);
    k_logits<<<(VOCAB + 31) / 32, 256>>>(out_W, out_b, out_logp);  // 4 rows/warp
    k_lse_part<<<LSE_PARTS, 256>>>(out_logp);
    k_lse_apply<<<(VOCAB + 255) / 256, 256>>>(out_logp);
}